// round 8
// baseline (speedup 1.0000x reference)
#include <cuda_runtime.h>
#include <cuda_bf16.h>

#define Bn 1024
#define Dn 512
#define On 256
#define BO (Bn * On)
#define DO (Dn * On)

// ---------------- device scratch (no allocations allowed) ----------------
__device__ float  g_SxP[8 * Dn];            // partial sums of (1-x) per 128-b chunk
__device__ float  g_rxpF[8 * DO];           // rel_x numerator partials (per 128-b split)
__device__ float  g_relxT[On * Dn];         // rel_x transposed [o][d]
__device__ float  g_xT[Dn * Bn];            // x transposed [d][b]
__device__ float  g_tT[On * Bn];            // t transposed [o][b]

// ---------------- Sx partials + x transpose ------------------------------
// grid (Dn/32=16, 8 b-splits), block 256
__global__ __launch_bounds__(256) void k_prepx_part(const float* __restrict__ x) {
    int d0 = blockIdx.x * 32;
    int bs = blockIdx.y;                  // 128 b's per split
    int b0 = bs * 128;
    int tid = threadIdx.x;
    __shared__ float tile[128][33];
#pragma unroll
    for (int p = 0; p < 16; p++) {
        int idx = p * 256 + tid;
        int row = idx >> 5, col = idx & 31;
        tile[row][col] = x[(b0 + row) * Dn + d0 + col];
    }
    __syncthreads();
    {
        int dt = tid & 31;
        int rt = tid >> 5;                // 0..7
        float s = 0.0f;
#pragma unroll
        for (int k = 0; k < 16; k++)
            s += 1.0f - tile[rt * 16 + k][dt];
        __shared__ float sh[8][33];
        sh[rt][dt] = s;
        __syncthreads();
        if (rt == 0) {
            float acc = 0.0f;
#pragma unroll
            for (int r = 0; r < 8; r++) acc += sh[r][dt];
            g_SxP[bs * Dn + d0 + dt] = acc;
        }
    }
#pragma unroll
    for (int p = 0; p < 16; p++) {
        int idx = p * 256 + tid;
        int b = idx & 127, d = idx >> 7;
        g_xT[(d0 + d) * Bn + b0 + b] = tile[b][d];
    }
}

// ---------------- t transpose --------------------------------------------
// grid (On/32=8, Bn/32=32), block 256
__global__ __launch_bounds__(256) void k_prept(const float* __restrict__ t) {
    int o0 = blockIdx.x * 32;
    int b0 = blockIdx.y * 32;
    int tid = threadIdx.x;
    __shared__ float tl[32][33];
#pragma unroll
    for (int p = 0; p < 4; p++) {
        int idx = p * 256 + tid;
        int row = idx >> 5, col = idx & 31;
        tl[row][col] = t[(b0 + row) * On + o0 + col];
    }
    __syncthreads();
#pragma unroll
    for (int p = 0; p < 4; p++) {
        int idx = p * 256 + tid;
        int row = idx >> 5, col = idx & 31;
        g_tT[(o0 + row) * Bn + b0 + col] = tl[col][row];
    }
}

// ---------------- rel_x numerator partials: sum_b max(x,t) ---------------
// grid (On/64=4, Dn/64=8, 8 b-splits); block 256; micro 4x4
__global__ __launch_bounds__(256, 2) void k_relx(const float* __restrict__ x,
                                                 const float* __restrict__ t) {
    int o0 = blockIdx.x * 64;
    int d0 = blockIdx.y * 64;
    int bs = blockIdx.z;
    __shared__ float xs[32][68];
    __shared__ float ts[32][68];
    int tid = threadIdx.x;
    int tx = tid & 15;   // o quad
    int ty = tid >> 4;   // d quad
    double a[16];
#pragma unroll
    for (int k = 0; k < 16; k++) a[k] = 0.0;
    for (int chunk = 0; chunk < 4; chunk++) {
        int bc = bs * 128 + chunk * 32;
        __syncthreads();
        for (int u = tid; u < 512; u += 256) {
            int r = u >> 4, c = u & 15;
            *(float4*)&xs[r][c * 4] = *(const float4*)&x[(bc + r) * Dn + d0 + c * 4];
            *(float4*)&ts[r][c * 4] = *(const float4*)&t[(bc + r) * On + o0 + c * 4];
        }
        __syncthreads();
        float f[16];
#pragma unroll
        for (int k = 0; k < 16; k++) f[k] = 0.0f;
#pragma unroll
        for (int kb = 0; kb < 32; kb++) {
            float4 xv = *(const float4*)&xs[kb][ty * 4];
            float4 tv = *(const float4*)&ts[kb][tx * 4];
            f[0]  += fmaxf(xv.x, tv.x);  f[1]  += fmaxf(xv.x, tv.y);
            f[2]  += fmaxf(xv.x, tv.z);  f[3]  += fmaxf(xv.x, tv.w);
            f[4]  += fmaxf(xv.y, tv.x);  f[5]  += fmaxf(xv.y, tv.y);
            f[6]  += fmaxf(xv.y, tv.z);  f[7]  += fmaxf(xv.y, tv.w);
            f[8]  += fmaxf(xv.z, tv.x);  f[9]  += fmaxf(xv.z, tv.y);
            f[10] += fmaxf(xv.z, tv.z);  f[11] += fmaxf(xv.z, tv.w);
            f[12] += fmaxf(xv.w, tv.x);  f[13] += fmaxf(xv.w, tv.y);
            f[14] += fmaxf(xv.w, tv.z);  f[15] += fmaxf(xv.w, tv.w);
        }
#pragma unroll
        for (int k = 0; k < 16; k++) a[k] += (double)f[k];
    }
    float* p = g_rxpF + (size_t)bs * DO;
#pragma unroll
    for (int i = 0; i < 4; i++) {
        int d_ = d0 + ty * 4 + i;
        int o_ = o0 + tx * 4;
        float4 v4;
        v4.x = (float)a[i * 4 + 0];
        v4.y = (float)a[i * 4 + 1];
        v4.z = (float)a[i * 4 + 2];
        v4.w = (float)a[i * 4 + 3];
        *(float4*)&p[d_ * On + o_] = v4;
    }
}

// ---------------- combine rel_x partials (+Sx) + transpose to [o][d] -----
__global__ __launch_bounds__(256) void k_transRel() {
    int i = blockIdx.x * 256 + threadIdx.x;  // [d][o] linear
    int d = i >> 8;
    int o = i & 255;
    double a = 0.0;
#pragma unroll
    for (int s = 0; s < 8; s++) a += (double)g_rxpF[(size_t)s * DO + i];
    double sx = 0.0;
#pragma unroll
    for (int s = 0; s < 8; s++) sx += (double)g_SxP[s * Dn + d];
    g_relxT[o * Dn + d] = (float)(1.0 - ((double)Bn - a) / sx);
}

// ---------------- solve both sides: grid 512 -----------------------------
// blocks [0,256): x-side  (threshold subset + lexicographic argmin)
// blocks [256,512): w-side (sort w col, scans, binary-search walk)
__global__ __launch_bounds__(256) void k_solve(const float* __restrict__ w,
                                               float* __restrict__ out) {
    int o = blockIdx.x & 255;
    int tid = threadIdx.x;
    __shared__ char buf[12288];
    __shared__ float redm[16];
    __shared__ int nlist;

    if (blockIdx.x < 256) {
        // ------------------ x-side ------------------
        float* rv = (float*)buf;            // 512 rel values (original d order)
        float* lr = (float*)(buf + 2048);   // subset r
        int*   ld = (int*)(buf + 4096);     // subset d
        float r1 = g_relxT[o * Dn + tid];
        float r2 = g_relxT[o * Dn + tid + 256];
        rv[tid] = r1;
        rv[tid + 256] = r2;
        // block min/max reduce
        float mn = fminf(r1, r2), mx = fmaxf(r1, r2);
#pragma unroll
        for (int s = 16; s > 0; s >>= 1) {
            mn = fminf(mn, __shfl_xor_sync(0xFFFFFFFFu, mn, s));
            mx = fmaxf(mx, __shfl_xor_sync(0xFFFFFFFFu, mx, s));
        }
        if ((tid & 31) == 0) { redm[tid >> 5] = mn; redm[8 + (tid >> 5)] = mx; }
        __syncthreads();
        float rmin = redm[0], rmax = redm[8];
#pragma unroll
        for (int i = 1; i < 8; i++) {
            rmin = fminf(rmin, redm[i]);
            rmax = fmaxf(rmax, redm[8 + i]);
        }
        // value-space binary search for smallest tested R with count >= 64
        float lo = rmin, hi = rmax, R = rmax;
        for (int it = 0; it < 8; it++) {
            float mid = 0.5f * (lo + hi);
            int c1 = __syncthreads_count(r1 <= mid);
            int c2 = __syncthreads_count(r2 <= mid);
            if (c1 + c2 >= 64) { R = mid; hi = mid; } else { lo = mid; }
        }
        // compact subset {d : r_d <= R}
        if (tid == 0) nlist = 0;
        __syncthreads();
        if (r1 <= R) { int p = atomicAdd(&nlist, 1); ld[p] = tid; lr[p] = r1; }
        if (r2 <= R) { int p = atomicAdd(&nlist, 1); ld[p] = tid + 256; lr[p] = r2; }
        __syncthreads();
        int L = nlist;
        // evaluate: argmin_d max(x[b,d], r_d), lexicographic (v, d) ties
        for (int bb = 0; bb < 4; bb++) {
            int b = bb * 256 + tid;
            float bv = 3.4e38f;
            int bd = Dn;
#pragma unroll 4
            for (int j = 0; j < L; j++) {
                float r = lr[j];
                int d = ld[j];
                float v = fmaxf(g_xT[d * Bn + b], r);
                if (v < bv || (v == bv && d < bd)) { bv = v; bd = d; }
            }
            if (bv > R) {   // certification failed (ultra-rare): exact full scan
                bv = 3.4e38f; bd = Dn;
                for (int d = 0; d < Dn; d++) {
                    float v = fmaxf(g_xT[d * Bn + b], rv[d]);
                    if (v < bv || (v == bv && d < bd)) { bv = v; bd = d; }
                }
            }
            out[b * On + o] = fmaxf(g_xT[bd * Bn + b], w[bd * On + o]);
        }
    } else {
        // ------------------ w-side ------------------
        float*  sv  = (float*)buf;            // original order
        float*  ss  = (float*)(buf + 2048);   // sorted ascending
        float*  pma = (float*)(buf + 4096);
        float*  pmb = (float*)(buf + 6144);
        __shared__ double sa[Dn];
        __shared__ double sb[Dn];
        for (int i = tid; i < Dn; i += 256) {
            float v = w[i * On + o];
            sv[i] = v;
            ss[i] = v;
        }
        __syncthreads();
        // bitonic sort ascending (32-bit)
        for (int k = 2; k <= Dn; k <<= 1) {
            for (int j = k >> 1; j > 0; j >>= 1) {
                for (int t2 = tid; t2 < Dn; t2 += 256) {
                    int ixj = t2 ^ j;
                    if (ixj > t2) {
                        bool up = ((t2 & k) == 0);
                        float a = ss[t2], b2 = ss[ixj];
                        if ((a > b2) == up) { ss[t2] = b2; ss[ixj] = a; }
                    }
                }
                __syncthreads();
            }
        }
        // parallel prefix-min (original order) + suffix-sum (sorted, double)
        for (int i = tid; i < Dn; i += 256) {
            pma[i] = sv[i];
            sa[i] = (double)ss[i];
        }
        __syncthreads();
        bool ping = true;
        for (int off = 1; off < Dn; off <<= 1) {
            float*  psrc = ping ? pma : pmb;
            float*  pdst = ping ? pmb : pma;
            double* ssrc = ping ? sa : sb;
            double* sdst = ping ? sb : sa;
            for (int i = tid; i < Dn; i += 256) {
                pdst[i] = (i >= off) ? fminf(psrc[i], psrc[i - off]) : psrc[i];
                sdst[i] = (i + off < Dn) ? ssrc[i] + ssrc[i + off] : ssrc[i];
            }
            __syncthreads();
            ping = !ping;
        }
        float*  pm  = ping ? pma : pmb;
        double* suf = ping ? sa : sb;
        double Sw = (double)Dn - suf[0];
        float gm = pm[Dn - 1];
        for (int b = tid; b < Bn; b += 256) {
            float tv = g_tT[o * Bn + b];
            int lo = 0, hi = Dn;
            while (lo < hi) {
                int m = (lo + hi) >> 1;
                if (ss[m] <= tv) lo = m + 1; else hi = m;
            }
            int c = lo;
            double sufc = (c < Dn) ? suf[c] : 0.0;
            double N = (double)c * (double)tv + sufc;
            float thr = (float)(1.0 - ((double)Dn - N) / Sw);
            int ind;
            if (gm <= thr) {
                lo = 0; hi = Dn - 1;
                while (lo < hi) {
                    int m = (lo + hi) >> 1;
                    if (pm[m] <= thr) hi = m; else lo = m + 1;
                }
                ind = lo;
            } else {
                lo = 0; hi = Dn - 1;
                while (lo < hi) {
                    int m = (lo + hi) >> 1;
                    if (pm[m] <= gm) hi = m; else lo = m + 1;
                }
                ind = lo;
            }
            out[BO + b * On + o] = fmaxf(g_xT[ind * Bn + b], w[ind * On + o]);
        }
    }
}

extern "C" void kernel_launch(void* const* d_in, const int* in_sizes, int n_in,
                              void* d_out, int out_size) {
    (void)in_sizes; (void)n_in; (void)out_size;
    const float* x = (const float*)d_in[0];
    const float* w = (const float*)d_in[1];
    const float* t = (const float*)d_in[2];
    float* out = (float*)d_out;

    k_prepx_part<<<dim3(16, 8), 256>>>(x);
    k_prept<<<dim3(8, 32), 256>>>(t);
    k_relx<<<dim3(On / 64, Dn / 64, 8), 256>>>(x, t);
    k_transRel<<<DO / 256, 256>>>();
    k_solve<<<512, 256>>>(w, out);
}

// round 9
// speedup vs baseline: 1.0187x; 1.0187x over previous
#include <cuda_runtime.h>
#include <cuda_bf16.h>

#define Bn 1024
#define Dn 512
#define On 256
#define BO (Bn * On)
#define DO (Dn * On)

// ---------------- device scratch (no allocations allowed) ----------------
__device__ float  g_SxP[8 * Dn];            // partial sums of (1-x) per 128-b chunk
__device__ float  g_rxpF[8 * DO];           // rel_x numerator partials [s][d][o]
__device__ float  g_xT[Dn * Bn];            // x transposed [d][b]
__device__ float  g_tT[On * Bn];            // t transposed [o][b]

// =========================================================================
// k_front: 448 blocks
//   [0,256):   rel_x numerator partials (sum_b max(x,t)), 4x4 micro tiles
//   [256,384): Sx partials + x transpose
//   [384,448): t transpose
// =========================================================================
__global__ __launch_bounds__(256, 2) void k_front(const float* __restrict__ x,
                                                  const float* __restrict__ t) {
    __shared__ char smem[18048];
    int tid = threadIdx.x;
    int blk = blockIdx.x;

    if (blk < 256) {
        // ---------------- rel_x partials ----------------
        float (*xs)[68] = (float(*)[68])smem;           // [32][68]
        float (*ts)[68] = (float(*)[68])(smem + 8704);  // [32][68]
        int o0 = (blk & 3) * 64;
        int d0 = ((blk >> 2) & 7) * 64;
        int bs = blk >> 5;
        int tx = tid & 15;   // o quad
        int ty = tid >> 4;   // d quad
        double a[16];
#pragma unroll
        for (int k = 0; k < 16; k++) a[k] = 0.0;
        for (int chunk = 0; chunk < 4; chunk++) {
            int bc = bs * 128 + chunk * 32;
            __syncthreads();
            for (int u = tid; u < 512; u += 256) {
                int r = u >> 4, c = u & 15;
                *(float4*)&xs[r][c * 4] = *(const float4*)&x[(bc + r) * Dn + d0 + c * 4];
                *(float4*)&ts[r][c * 4] = *(const float4*)&t[(bc + r) * On + o0 + c * 4];
            }
            __syncthreads();
            float f[16];
#pragma unroll
            for (int k = 0; k < 16; k++) f[k] = 0.0f;
#pragma unroll
            for (int kb = 0; kb < 32; kb++) {
                float4 xv = *(const float4*)&xs[kb][ty * 4];
                float4 tv = *(const float4*)&ts[kb][tx * 4];
                f[0]  += fmaxf(xv.x, tv.x);  f[1]  += fmaxf(xv.x, tv.y);
                f[2]  += fmaxf(xv.x, tv.z);  f[3]  += fmaxf(xv.x, tv.w);
                f[4]  += fmaxf(xv.y, tv.x);  f[5]  += fmaxf(xv.y, tv.y);
                f[6]  += fmaxf(xv.y, tv.z);  f[7]  += fmaxf(xv.y, tv.w);
                f[8]  += fmaxf(xv.z, tv.x);  f[9]  += fmaxf(xv.z, tv.y);
                f[10] += fmaxf(xv.z, tv.z);  f[11] += fmaxf(xv.z, tv.w);
                f[12] += fmaxf(xv.w, tv.x);  f[13] += fmaxf(xv.w, tv.y);
                f[14] += fmaxf(xv.w, tv.z);  f[15] += fmaxf(xv.w, tv.w);
            }
#pragma unroll
            for (int k = 0; k < 16; k++) a[k] += (double)f[k];
        }
        float* p = g_rxpF + (size_t)bs * DO;
#pragma unroll
        for (int i = 0; i < 4; i++) {
            int d_ = d0 + ty * 4 + i;
            int o_ = o0 + tx * 4;
            float4 v4;
            v4.x = (float)a[i * 4 + 0];
            v4.y = (float)a[i * 4 + 1];
            v4.z = (float)a[i * 4 + 2];
            v4.w = (float)a[i * 4 + 3];
            *(float4*)&p[d_ * On + o_] = v4;
        }
    } else if (blk < 384) {
        // ---------------- Sx partials + x transpose ----------------
        float (*tile)[33] = (float(*)[33])smem;            // [128][33] = 16896B
        float (*sh)[33]   = (float(*)[33])(smem + 16896);  // [8][33]   = 1056B
        int j = blk - 256;
        int d0 = (j & 15) * 32;
        int bs = j >> 4;
        int b0 = bs * 128;
#pragma unroll
        for (int p = 0; p < 16; p++) {
            int idx = p * 256 + tid;
            int row = idx >> 5, col = idx & 31;
            tile[row][col] = x[(b0 + row) * Dn + d0 + col];
        }
        __syncthreads();
        {
            int dt = tid & 31;
            int rt = tid >> 5;                // 0..7
            float s = 0.0f;
#pragma unroll
            for (int k = 0; k < 16; k++)
                s += 1.0f - tile[rt * 16 + k][dt];
            sh[rt][dt] = s;
            __syncthreads();
            if (rt == 0) {
                float acc = 0.0f;
#pragma unroll
                for (int r = 0; r < 8; r++) acc += sh[r][dt];
                g_SxP[bs * Dn + d0 + dt] = acc;
            }
        }
#pragma unroll
        for (int p = 0; p < 16; p++) {
            int idx = p * 256 + tid;
            int b = idx & 127, d = idx >> 7;
            g_xT[(d0 + d) * Bn + b0 + b] = tile[b][d];
        }
    } else {
        // ---------------- t transpose ----------------
        float (*tile)[33] = (float(*)[33])smem;  // [128][33]
        int j = blk - 384;                        // 0..63
        int o0 = (j & 7) * 32;
        int b0 = (j >> 3) * 128;
#pragma unroll
        for (int p = 0; p < 16; p++) {
            int idx = p * 256 + tid;
            int row = idx >> 5, col = idx & 31;
            tile[row][col] = t[(b0 + row) * On + o0 + col];
        }
        __syncthreads();
#pragma unroll
        for (int p = 0; p < 16; p++) {
            int idx = p * 256 + tid;
            int b = idx & 127, o = idx >> 7;
            g_tT[(o0 + o) * Bn + b0 + b] = tile[b][o];
        }
    }
}

// =========================================================================
// k_solve: 512 blocks
//   [0,256):   x-side — inline rel_x combine, threshold subset, argmin
//   [256,512): w-side — sort w col, scans, binary-search walk
// =========================================================================
__global__ __launch_bounds__(256) void k_solve(const float* __restrict__ w,
                                               float* __restrict__ out) {
    int o = blockIdx.x & 255;
    int tid = threadIdx.x;
    __shared__ char buf[12288];
    __shared__ float redm[16];
    __shared__ int nlist;

    if (blockIdx.x < 256) {
        // ------------------ x-side ------------------
        float* rv = (float*)buf;            // 512 rel values (original d order)
        float* lr = (float*)(buf + 2048);   // subset r
        int*   ld = (int*)(buf + 4096);     // subset d
        // inline combine (same summation order as old k_transRel: s = 0..7)
        int d1 = tid, d2 = tid + 256;
        double a1 = 0.0, a2 = 0.0;
#pragma unroll
        for (int s = 0; s < 8; s++) {
            a1 += (double)g_rxpF[(size_t)s * DO + d1 * On + o];
            a2 += (double)g_rxpF[(size_t)s * DO + d2 * On + o];
        }
        double sx1 = 0.0, sx2 = 0.0;
#pragma unroll
        for (int s = 0; s < 8; s++) {
            sx1 += (double)g_SxP[s * Dn + d1];
            sx2 += (double)g_SxP[s * Dn + d2];
        }
        float r1 = (float)(1.0 - ((double)Bn - a1) / sx1);
        float r2 = (float)(1.0 - ((double)Bn - a2) / sx2);
        rv[d1] = r1;
        rv[d2] = r2;
        // block min/max reduce
        float mn = fminf(r1, r2), mx = fmaxf(r1, r2);
#pragma unroll
        for (int s = 16; s > 0; s >>= 1) {
            mn = fminf(mn, __shfl_xor_sync(0xFFFFFFFFu, mn, s));
            mx = fmaxf(mx, __shfl_xor_sync(0xFFFFFFFFu, mx, s));
        }
        if ((tid & 31) == 0) { redm[tid >> 5] = mn; redm[8 + (tid >> 5)] = mx; }
        __syncthreads();
        float rmin = redm[0], rmax = redm[8];
#pragma unroll
        for (int i = 1; i < 8; i++) {
            rmin = fminf(rmin, redm[i]);
            rmax = fmaxf(rmax, redm[8 + i]);
        }
        // value-space binary search for smallest tested R with count >= 64
        float lo = rmin, hi = rmax, R = rmax;
        for (int it = 0; it < 8; it++) {
            float mid = 0.5f * (lo + hi);
            int c1 = __syncthreads_count(r1 <= mid);
            int c2 = __syncthreads_count(r2 <= mid);
            if (c1 + c2 >= 64) { R = mid; hi = mid; } else { lo = mid; }
        }
        // compact subset {d : r_d <= R}
        if (tid == 0) nlist = 0;
        __syncthreads();
        if (r1 <= R) { int p = atomicAdd(&nlist, 1); ld[p] = d1; lr[p] = r1; }
        if (r2 <= R) { int p = atomicAdd(&nlist, 1); ld[p] = d2; lr[p] = r2; }
        __syncthreads();
        int L = nlist;
        // evaluate: argmin_d max(x[b,d], r_d), lexicographic (v, d) ties
        for (int bb = 0; bb < 4; bb++) {
            int b = bb * 256 + tid;
            float bv = 3.4e38f;
            int bd = Dn;
#pragma unroll 4
            for (int j = 0; j < L; j++) {
                float r = lr[j];
                int d = ld[j];
                float v = fmaxf(g_xT[d * Bn + b], r);
                if (v < bv || (v == bv && d < bd)) { bv = v; bd = d; }
            }
            if (bv > R) {   // certification failed (ultra-rare): exact full scan
                bv = 3.4e38f; bd = Dn;
                for (int d = 0; d < Dn; d++) {
                    float v = fmaxf(g_xT[d * Bn + b], rv[d]);
                    if (v < bv || (v == bv && d < bd)) { bv = v; bd = d; }
                }
            }
            out[b * On + o] = fmaxf(g_xT[bd * Bn + b], w[bd * On + o]);
        }
    } else {
        // ------------------ w-side ------------------
        float*  sv  = (float*)buf;            // original order
        float*  ss  = (float*)(buf + 2048);   // sorted ascending
        float*  pma = (float*)(buf + 4096);
        float*  pmb = (float*)(buf + 6144);
        __shared__ double sa[Dn];
        __shared__ double sb[Dn];
        for (int i = tid; i < Dn; i += 256) {
            float v = w[i * On + o];
            sv[i] = v;
            ss[i] = v;
        }
        __syncthreads();
        // bitonic sort ascending (32-bit)
        for (int k = 2; k <= Dn; k <<= 1) {
            for (int j = k >> 1; j > 0; j >>= 1) {
                for (int t2 = tid; t2 < Dn; t2 += 256) {
                    int ixj = t2 ^ j;
                    if (ixj > t2) {
                        bool up = ((t2 & k) == 0);
                        float a = ss[t2], b2 = ss[ixj];
                        if ((a > b2) == up) { ss[t2] = b2; ss[ixj] = a; }
                    }
                }
                __syncthreads();
            }
        }
        // parallel prefix-min (original order) + suffix-sum (sorted, double)
        for (int i = tid; i < Dn; i += 256) {
            pma[i] = sv[i];
            sa[i] = (double)ss[i];
        }
        __syncthreads();
        bool ping = true;
        for (int off = 1; off < Dn; off <<= 1) {
            float*  psrc = ping ? pma : pmb;
            float*  pdst = ping ? pmb : pma;
            double* ssrc = ping ? sa : sb;
            double* sdst = ping ? sb : sa;
            for (int i = tid; i < Dn; i += 256) {
                pdst[i] = (i >= off) ? fminf(psrc[i], psrc[i - off]) : psrc[i];
                sdst[i] = (i + off < Dn) ? ssrc[i] + ssrc[i + off] : ssrc[i];
            }
            __syncthreads();
            ping = !ping;
        }
        float*  pm  = ping ? pma : pmb;
        double* suf = ping ? sa : sb;
        double Sw = (double)Dn - suf[0];
        float gm = pm[Dn - 1];
        for (int b = tid; b < Bn; b += 256) {
            float tv = g_tT[o * Bn + b];
            int lo = 0, hi = Dn;
            while (lo < hi) {
                int m = (lo + hi) >> 1;
                if (ss[m] <= tv) lo = m + 1; else hi = m;
            }
            int c = lo;
            double sufc = (c < Dn) ? suf[c] : 0.0;
            double N = (double)c * (double)tv + sufc;
            float thr = (float)(1.0 - ((double)Dn - N) / Sw);
            int ind;
            if (gm <= thr) {
                lo = 0; hi = Dn - 1;
                while (lo < hi) {
                    int m = (lo + hi) >> 1;
                    if (pm[m] <= thr) hi = m; else lo = m + 1;
                }
                ind = lo;
            } else {
                lo = 0; hi = Dn - 1;
                while (lo < hi) {
                    int m = (lo + hi) >> 1;
                    if (pm[m] <= gm) hi = m; else lo = m + 1;
                }
                ind = lo;
            }
            out[BO + b * On + o] = fmaxf(g_xT[ind * Bn + b], w[ind * On + o]);
        }
    }
}

extern "C" void kernel_launch(void* const* d_in, const int* in_sizes, int n_in,
                              void* d_out, int out_size) {
    (void)in_sizes; (void)n_in; (void)out_size;
    const float* x = (const float*)d_in[0];
    const float* w = (const float*)d_in[1];
    const float* t = (const float*)d_in[2];
    float* out = (float*)d_out;

    k_front<<<448, 256>>>(x, t);
    k_solve<<<512, 256>>>(w, out);
}